// round 1
// baseline (speedup 1.0000x reference)
#include <cuda_runtime.h>
#include <math.h>

#define NN 50000
#define EE 500000
#define HD 128
#define NH 8
#define DD 16
#define CLAMPV 5.0f

// ---------------- scratch (static device allocations are allowed) -----------
__device__ float g_Qh[NN * HD];
__device__ float g_Kh[NN * HD];
__device__ float g_Vh[NN * HD];
__device__ float g_eexp[(size_t)EE * NH];
__device__ float g_denom[NN * NH];
__device__ float g_rowV[NN * HD];

// ---------------- helpers ----------------------------------------------------
__device__ __forceinline__ void red_add_v4(float* addr, float a, float b, float c, float d) {
    asm volatile("red.global.add.v4.f32 [%0], {%1,%2,%3,%4};"
                 :: "l"(addr), "f"(a), "f"(b), "f"(c), "f"(d)
                 : "memory");
}

// ---------------- zero scratch ------------------------------------------------
__global__ void zero_kernel() {
    int stride = gridDim.x * blockDim.x;
    int total = NN * HD + NN * NH;
    for (int i = blockIdx.x * blockDim.x + threadIdx.x; i < total; i += stride) {
        if (i < NN * HD) g_rowV[i] = 0.f;
        else             g_denom[i - NN * HD] = 0.f;
    }
}

// ---------------- node GEMM: Qh/Kh/Vh = x @ W + b ----------------------------
// 64x128 tile, 256 threads, 4x8 microtile, K=128
__global__ __launch_bounds__(256) void node_gemm(
    const float* __restrict__ x,
    const float* __restrict__ WQ, const float* __restrict__ bQ,
    const float* __restrict__ WK, const float* __restrict__ bK,
    const float* __restrict__ WV, const float* __restrict__ bV,
    float* __restrict__ d_out)
{
    const int which = blockIdx.y;
    const float* W    = (which == 0) ? WQ : (which == 1) ? WK : WV;
    const float* bias = (which == 0) ? bQ : (which == 1) ? bK : bV;
    float* out        = (which == 0) ? g_Qh : (which == 1) ? g_Kh : g_Vh;

    __shared__ float As[64 * 16];
    __shared__ float Bs[16 * 128];

    const int tid = threadIdx.x;
    const int tx = tid & 15, ty = tid >> 4;
    const int m0 = blockIdx.x * 64;

    const int ar = tid >> 2;          // 0..63
    const int ac = (tid & 3) * 4;     // 0,4,8,12
    const int brow = tid >> 4;        // 0..15
    const int bcol = (tid & 15) * 8;  // 0..120

    float acc[4][8];
    #pragma unroll
    for (int i = 0; i < 4; i++)
        #pragma unroll
        for (int j = 0; j < 8; j++) acc[i][j] = 0.f;

    for (int k0 = 0; k0 < 128; k0 += 16) {
        float4 av = make_float4(0.f, 0.f, 0.f, 0.f);
        int m = m0 + ar;
        if (m < NN) av = *(const float4*)&x[(size_t)m * 128 + k0 + ac];
        *(float4*)&As[ar * 16 + ac] = av;
        *(float4*)&Bs[brow * 128 + bcol]     = *(const float4*)&W[(size_t)(k0 + brow) * 128 + bcol];
        *(float4*)&Bs[brow * 128 + bcol + 4] = *(const float4*)&W[(size_t)(k0 + brow) * 128 + bcol + 4];
        __syncthreads();
        #pragma unroll
        for (int k = 0; k < 16; k++) {
            float a[4], b[8];
            #pragma unroll
            for (int i = 0; i < 4; i++) a[i] = As[(ty * 4 + i) * 16 + k];
            #pragma unroll
            for (int j = 0; j < 8; j++) b[j] = Bs[k * 128 + tx * 8 + j];
            #pragma unroll
            for (int i = 0; i < 4; i++)
                #pragma unroll
                for (int j = 0; j < 8; j++)
                    acc[i][j] = fmaf(a[i], b[j], acc[i][j]);
        }
        __syncthreads();
    }

    #pragma unroll
    for (int i = 0; i < 4; i++) {
        int m = m0 + ty * 4 + i;
        if (m >= NN) continue;
        #pragma unroll
        for (int j = 0; j < 8; j++) {
            int c = tx * 8 + j;
            float v = acc[i][j] + bias[c];
            out[(size_t)m * 128 + c] = v;
            if (which == 0) d_out[(size_t)m * 128 + c] = v;  // Vo initialized with Qh
        }
    }
}

// ---------------- edge GEMM + fused epilogue ---------------------------------
// Computes Ex tile (64 edges x 128 cols = 4 heads), then:
//   conn = Kh[src] + Qh[dst] + signed_sqrt(Ex1*Ex2)   -> d_out (2nd output)
//   score = clip(conn . Aw, +-5); eexp = exp(score)   -> g_eexp
//   atomic denom[dst,h] += eexp
__global__ __launch_bounds__(256) void edge_gemm(
    const float* __restrict__ ea,
    const float* __restrict__ WE, const float* __restrict__ bE,
    const int* __restrict__ edge_index,
    const float* __restrict__ Aw,
    float* __restrict__ d_out)
{
    __shared__ float As[64 * 16];
    __shared__ float Bs[16 * 128];
    __shared__ float Ex[64 * 128];
    __shared__ float AwS[128];   // [d][h] = d*8+h

    const int tid = threadIdx.x;
    const int tx = tid & 15, ty = tid >> 4;
    const int m0 = blockIdx.x * 64;
    const int n0 = blockIdx.y * 128;   // 0 or 128 (heads 0-3 / 4-7)

    if (tid < 128) AwS[tid] = Aw[tid];

    const int ar = tid >> 2;
    const int ac = (tid & 3) * 4;
    const int brow = tid >> 4;
    const int bcol = (tid & 15) * 8;

    float acc[4][8];
    #pragma unroll
    for (int i = 0; i < 4; i++)
        #pragma unroll
        for (int j = 0; j < 8; j++) acc[i][j] = 0.f;

    for (int k0 = 0; k0 < 128; k0 += 16) {
        float4 av = make_float4(0.f, 0.f, 0.f, 0.f);
        int m = m0 + ar;
        if (m < EE) av = *(const float4*)&ea[(size_t)m * 128 + k0 + ac];
        *(float4*)&As[ar * 16 + ac] = av;
        *(float4*)&Bs[brow * 128 + bcol]     = *(const float4*)&WE[(size_t)(k0 + brow) * 256 + n0 + bcol];
        *(float4*)&Bs[brow * 128 + bcol + 4] = *(const float4*)&WE[(size_t)(k0 + brow) * 256 + n0 + bcol + 4];
        __syncthreads();
        #pragma unroll
        for (int k = 0; k < 16; k++) {
            float a[4], b[8];
            #pragma unroll
            for (int i = 0; i < 4; i++) a[i] = As[(ty * 4 + i) * 16 + k];
            #pragma unroll
            for (int j = 0; j < 8; j++) b[j] = Bs[k * 128 + tx * 8 + j];
            #pragma unroll
            for (int i = 0; i < 4; i++)
                #pragma unroll
                for (int j = 0; j < 8; j++)
                    acc[i][j] = fmaf(a[i], b[j], acc[i][j]);
        }
        __syncthreads();
    }

    // stash Ex (+bias) to smem
    #pragma unroll
    for (int i = 0; i < 4; i++) {
        int r = ty * 4 + i;
        #pragma unroll
        for (int j = 0; j < 8; j++) {
            int c = tx * 8 + j;
            Ex[r * 128 + c] = acc[i][j] + bE[n0 + c];
        }
    }
    __syncthreads();

    float* connOut = d_out + (size_t)NN * 128;

    // conn: 64 edges * 4 heads * 16 dims = 4096 values; each thread 16.
    // Each (el,g,d) pair is owned by exactly one thread: safe to overwrite
    // Ex[el][g*32+d] in place after reading both halves.
    for (int idx = tid; idx < 64 * 64; idx += 256) {
        int el  = idx >> 6;
        int rem = idx & 63;
        int g   = rem >> 4;
        int d   = rem & 15;
        int e   = m0 + el;
        float x1 = Ex[el * 128 + g * 32 + d];
        float x2 = Ex[el * 128 + g * 32 + 16 + d];
        float s2 = x1 * x2;
        float sc2 = copysignf(sqrtf(fabsf(s2)), s2);
        if (e < EE) {
            int h = blockIdx.y * 4 + g;
            int src = edge_index[e];
            int dst = edge_index[EE + e];
            float conn = g_Kh[(size_t)src * 128 + h * 16 + d]
                       + g_Qh[(size_t)dst * 128 + h * 16 + d] + sc2;
            connOut[(size_t)e * 128 + h * 16 + d] = conn;
            Ex[el * 128 + g * 32 + d] = conn;
        }
    }
    __syncthreads();

    // score per (edge, head): 256 threads = 64 edges x 4 heads
    {
        int el = tid >> 2;
        int g  = tid & 3;
        int e  = m0 + el;
        if (e < EE) {
            int h = blockIdx.y * 4 + g;
            float s = 0.f;
            #pragma unroll
            for (int d = 0; d < 16; d++)
                s = fmaf(Ex[el * 128 + g * 32 + d], AwS[d * 8 + h], s);
            s = fminf(fmaxf(s, -CLAMPV), CLAMPV);
            float ee = expf(s);
            g_eexp[(size_t)e * 8 + h] = ee;
            int dst = edge_index[EE + e];
            atomicAdd(&g_denom[dst * 8 + h], ee);
        }
    }
}

// ---------------- aggregation: warp per edge ---------------------------------
__global__ __launch_bounds__(256) void aggregate(
    const int* __restrict__ edge_index,
    float* __restrict__ d_out)
{
    const int warp = threadIdx.x >> 5;
    const int lane = threadIdx.x & 31;
    const size_t e = (size_t)blockIdx.x * 8 + warp;
    if (e >= EE) return;

    const int src = edge_index[e];
    const int dst = edge_index[EE + e];
    const int h = lane >> 2;   // 4 lanes per head (4 floats each = 16 dims)

    float den  = g_denom[dst * 8 + h];
    float attn = g_eexp[e * 8 + h] / (den + 1e-16f);

    const float4* Vh4   = (const float4*)g_Vh;
    const float4* conn4 = (const float4*)(d_out + (size_t)NN * 128);
    float4 v = Vh4[(size_t)src * 32 + lane];
    float4 c = conn4[e * 32 + lane];

    float4* out4 = (float4*)d_out;
    float4* row4 = (float4*)g_rowV;
    red_add_v4((float*)&out4[(size_t)dst * 32 + lane], v.x * attn, v.y * attn, v.z * attn, v.w * attn);
    red_add_v4((float*)&row4[(size_t)dst * 32 + lane], c.x * attn, c.y * attn, c.z * attn, c.w * attn);
}

// ---------------- finalize: Vo += rowV @ VeRow per head ----------------------
__global__ __launch_bounds__(128) void finalize(
    const float* __restrict__ VeRow,
    float* __restrict__ d_out)
{
    __shared__ float Vs[2048];  // [d][h][c] = d*128 + h*16 + c
    const int tid = threadIdx.x;
    for (int i = tid; i < 2048; i += 128) Vs[i] = VeRow[i];
    __syncthreads();

    const int h = tid >> 4, c = tid & 15;
    const int n0 = blockIdx.x * 32;
    const int nend = (n0 + 32 < NN) ? n0 + 32 : NN;
    for (int n = n0; n < nend; n++) {
        float acc = 0.f;
        #pragma unroll
        for (int d = 0; d < 16; d++)
            acc = fmaf(g_rowV[(size_t)n * 128 + h * 16 + d], Vs[d * 128 + h * 16 + c], acc);
        d_out[(size_t)n * 128 + h * 16 + c] += acc;
    }
}

// ---------------- launch ------------------------------------------------------
extern "C" void kernel_launch(void* const* d_in, const int* in_sizes, int n_in,
                              void* d_out, int out_size)
{
    const float* x    = (const float*)d_in[0];
    const float* ea   = (const float*)d_in[1];
    const int*   eidx = (const int*)  d_in[2];
    const float* WQ   = (const float*)d_in[3];
    const float* bQ   = (const float*)d_in[4];
    const float* WK   = (const float*)d_in[5];
    const float* bK   = (const float*)d_in[6];
    const float* WE   = (const float*)d_in[7];
    const float* bE   = (const float*)d_in[8];
    const float* WV   = (const float*)d_in[9];
    const float* bV   = (const float*)d_in[10];
    const float* Aw   = (const float*)d_in[11];
    const float* VeRow= (const float*)d_in[12];
    float* out = (float*)d_out;

    zero_kernel<<<1024, 256>>>();

    dim3 gn((NN + 63) / 64, 3);
    node_gemm<<<gn, 256>>>(x, WQ, bQ, WK, bK, WV, bV, out);

    dim3 ge((EE + 63) / 64, 2);
    edge_gemm<<<ge, 256>>>(ea, WE, bE, eidx, Aw, out);

    aggregate<<<(EE + 7) / 8, 256>>>(eidx, out);

    finalize<<<(NN + 31) / 32, 128>>>(VeRow, out);
}